// round 7
// baseline (speedup 1.0000x reference)
#include <cuda_runtime.h>
#include <cuda_bf16.h>
#include <math.h>
#include <stdint.h>

#define BSZ 2
#define SEQ 2048
#define DIM 1024
#define NH  16
#define HD  64
#define SCALE 0.125f

// Scratch (no cudaMalloc allowed)
__device__ float g_qkv[(size_t)BSZ * SEQ * 3 * DIM];   // [B,S,3D]
__device__ float g_attn[(size_t)BSZ * SEQ * DIM];      // [B,S,D]

// ---------------------------------------------------------------------------
// helpers
// ---------------------------------------------------------------------------
__device__ __forceinline__ uint32_t f2t(float x) {
    uint32_t u; asm("cvt.rna.tf32.f32 %0, %1;" : "=r"(u) : "f"(x)); return u;
}
__device__ __forceinline__ float tf32r(float x) { return __uint_as_float(f2t(x)); }

__device__ __forceinline__ void mma8(float* c, const uint32_t* a, const uint32_t* b) {
    asm volatile(
        "mma.sync.aligned.m16n8k8.row.col.f32.tf32.tf32.f32 "
        "{%0,%1,%2,%3}, {%4,%5,%6,%7}, {%8,%9}, {%0,%1,%2,%3};\n"
        : "+f"(c[0]), "+f"(c[1]), "+f"(c[2]), "+f"(c[3])
        : "r"(a[0]), "r"(a[1]), "r"(a[2]), "r"(a[3]), "r"(b[0]), "r"(b[1]));
}

__device__ __forceinline__ void mma16(float* c, const uint32_t* a, uint32_t b0, uint32_t b1) {
    asm volatile(
        "mma.sync.aligned.m16n8k16.row.col.f32.bf16.bf16.f32 "
        "{%0,%1,%2,%3}, {%4,%5,%6,%7}, {%8,%9}, {%0,%1,%2,%3};\n"
        : "+f"(c[0]), "+f"(c[1]), "+f"(c[2]), "+f"(c[3])
        : "r"(a[0]), "r"(a[1]), "r"(a[2]), "r"(a[3]), "r"(b0), "r"(b1));
}

__device__ __forceinline__ void split2(float a, float b, uint32_t& h, uint32_t& l) {
    __nv_bfloat16 ah = __float2bfloat16(a), bh = __float2bfloat16(b);
    __nv_bfloat16 al = __float2bfloat16(a - __bfloat162float(ah));
    __nv_bfloat16 bl = __float2bfloat16(b - __bfloat162float(bh));
    __nv_bfloat162 hv, lv;
    hv.x = ah; hv.y = bh; lv.x = al; lv.y = bl;
    h = *reinterpret_cast<uint32_t*>(&hv);
    l = *reinterpret_cast<uint32_t*>(&lv);
}

// ---------------------------------------------------------------------------
// bf16 GEMM, 3-term split, DOUBLE-BUFFERED smem + register prefetch,
// ONE __syncthreads per K-tile. Block 128x128, BK=32, 256 thr, 8 warps 4x2.
// Dynamic smem: 2 stages x {Ah,Al,Bh,Bl}[128][40] bf16 = 81,920 B.
// ---------------------------------------------------------------------------
#define GTILE (128 * 40)
#define GEMM_SMEM_BYTES (8 * GTILE * 2)

template<int EPI>
__global__ __launch_bounds__(256) void gemm_bf16(
    const float* __restrict__ A, const float* __restrict__ B,
    const float* __restrict__ bias, const float* __restrict__ gamma,
    float* __restrict__ C, int M, int N, int K)
{
    extern __shared__ __nv_bfloat16 gsm[];
    __nv_bfloat16* AhS = gsm;                 // [2][128][40]
    __nv_bfloat16* AlS = AhS + 2 * GTILE;
    __nv_bfloat16* BhS = AlS + 2 * GTILE;
    __nv_bfloat16* BlS = BhS + 2 * GTILE;

    int t = threadIdx.x, lane = t & 31, w = t >> 5;
    int wy = w >> 1, wx = w & 1;

    const float* Ab = A + (size_t)blockIdx.y * 128 * K;
    const float* Bb = B + (size_t)blockIdx.x * 128;

    float acc[2][8][4];
    #pragma unroll
    for (int mt = 0; mt < 2; mt++)
        #pragma unroll
        for (int nt = 0; nt < 8; nt++)
            #pragma unroll
            for (int i = 0; i < 4; i++) acc[mt][nt][i] = 0.f;

    float4 aR[4];
    float  bR[4][4];

    // prefetch tile 0
    #pragma unroll
    for (int i = 0; i < 4; i++) {
        int idx = t + i * 256;
        int r = idx >> 3, c4 = (idx & 7) * 4;
        aR[i] = *(const float4*)(Ab + (size_t)r * K + c4);
    }
    #pragma unroll
    for (int i = 0; i < 4; i++) {
        int idx = t + i * 256;
        int n = idx & 127, kc = idx >> 7;
        #pragma unroll
        for (int j = 0; j < 4; j++)
            bR[i][j] = Bb[(size_t)(kc * 4 + j) * N + n];
    }

    const int ITERS = K / 32;
    for (int it = 0; it < ITERS; it++) {
        int st = (it & 1) * GTILE;
        __nv_bfloat16* Ah = AhS + st;
        __nv_bfloat16* Al = AlS + st;
        __nv_bfloat16* Bh = BhS + st;
        __nv_bfloat16* Bl = BlS + st;

        // store prefetched regs -> current stage
        #pragma unroll
        for (int i = 0; i < 4; i++) {
            int idx = t + i * 256;
            int r = idx >> 3, c4 = (idx & 7) * 4;
            uint32_t h01, l01, h23, l23;
            split2(aR[i].x, aR[i].y, h01, l01);
            split2(aR[i].z, aR[i].w, h23, l23);
            *(uint2*)&Ah[r * 40 + c4] = make_uint2(h01, h23);
            *(uint2*)&Al[r * 40 + c4] = make_uint2(l01, l23);
        }
        #pragma unroll
        for (int i = 0; i < 4; i++) {
            int idx = t + i * 256;
            int n = idx & 127, kc = idx >> 7;
            uint32_t h01, l01, h23, l23;
            split2(bR[i][0], bR[i][1], h01, l01);
            split2(bR[i][2], bR[i][3], h23, l23);
            *(uint2*)&Bh[n * 40 + kc * 4] = make_uint2(h01, h23);
            *(uint2*)&Bl[n * 40 + kc * 4] = make_uint2(l01, l23);
        }
        __syncthreads();   // single barrier per tile (double-buffer safe)

        // issue gmem loads for next tile
        if (it + 1 < ITERS) {
            int k0n = (it + 1) * 32;
            #pragma unroll
            for (int i = 0; i < 4; i++) {
                int idx = t + i * 256;
                int r = idx >> 3, c4 = (idx & 7) * 4;
                aR[i] = *(const float4*)(Ab + (size_t)r * K + k0n + c4);
            }
            #pragma unroll
            for (int i = 0; i < 4; i++) {
                int idx = t + i * 256;
                int n = idx & 127, kc = idx >> 7;
                #pragma unroll
                for (int j = 0; j < 4; j++)
                    bR[i][j] = Bb[(size_t)(k0n + kc * 4 + j) * N + n];
            }
        }

        // mma phase
        #pragma unroll
        for (int ks = 0; ks < 2; ks++) {
            int kb = ks * 16 + (lane & 3) * 2;
            uint32_t ah[2][4], al[2][4];
            #pragma unroll
            for (int mt = 0; mt < 2; mt++) {
                int r = wy * 32 + mt * 16 + (lane >> 2);
                ah[mt][0] = *(uint32_t*)&Ah[r * 40 + kb];
                ah[mt][1] = *(uint32_t*)&Ah[(r + 8) * 40 + kb];
                ah[mt][2] = *(uint32_t*)&Ah[r * 40 + kb + 8];
                ah[mt][3] = *(uint32_t*)&Ah[(r + 8) * 40 + kb + 8];
                al[mt][0] = *(uint32_t*)&Al[r * 40 + kb];
                al[mt][1] = *(uint32_t*)&Al[(r + 8) * 40 + kb];
                al[mt][2] = *(uint32_t*)&Al[r * 40 + kb + 8];
                al[mt][3] = *(uint32_t*)&Al[(r + 8) * 40 + kb + 8];
            }
            #pragma unroll
            for (int nt = 0; nt < 8; nt++) {
                int n = wx * 64 + nt * 8 + (lane >> 2);
                uint32_t bh0 = *(uint32_t*)&Bh[n * 40 + kb];
                uint32_t bh1 = *(uint32_t*)&Bh[n * 40 + kb + 8];
                uint32_t bl0 = *(uint32_t*)&Bl[n * 40 + kb];
                uint32_t bl1 = *(uint32_t*)&Bl[n * 40 + kb + 8];
                #pragma unroll
                for (int mt = 0; mt < 2; mt++) {
                    mma16(acc[mt][nt], ah[mt], bh0, bh1);
                    mma16(acc[mt][nt], al[mt], bh0, bh1);
                    mma16(acc[mt][nt], ah[mt], bl0, bl1);
                }
            }
        }
    }

    // Epilogue (registers only — no smem dependency)
    int r_base = blockIdx.y * 128 + wy * 32 + (lane >> 2);
    int c_base = blockIdx.x * 128 + wx * 64 + 2 * (lane & 3);
    #pragma unroll
    for (int nt = 0; nt < 8; nt++) {
        int col = c_base + nt * 8;
        float2 bi = *(const float2*)&bias[col];
        float g0 = 1.f, g1 = 1.f;
        if (EPI) {
            float2 gm = *(const float2*)&gamma[col];
            g0 = gm.x + 1.f; g1 = gm.y + 1.f;
        }
        #pragma unroll
        for (int mt = 0; mt < 2; mt++) {
            int ra = r_base + mt * 16;
            float2 v0, v1;
            v0.x = acc[mt][nt][0] + bi.x;
            v0.y = acc[mt][nt][1] + bi.y;
            v1.x = acc[mt][nt][2] + bi.x;
            v1.y = acc[mt][nt][3] + bi.y;
            if (EPI) { v0.x *= g0; v0.y *= g1; v1.x *= g0; v1.y *= g1; }
            *(float2*)(C + (size_t)ra * N + col)       = v0;
            *(float2*)(C + (size_t)(ra + 8) * N + col) = v1;
        }
    }
}

// ---------------------------------------------------------------------------
// Flash attention, tf32 warp mma, SOFTWARE-PIPELINED loads:
//   store K(i); sync; issue V(i) loads; QK mma; softmax; store V(i); sync;
//   issue K(i+1) loads; PV mma.  Every gmem load retires under an mma phase.
// ---------------------------------------------------------------------------
__global__ __launch_bounds__(128) void attn_tf32(
    const float* __restrict__ qkv, const int* __restrict__ mask,
    float* __restrict__ out)
{
    extern __shared__ float sm[];
    float* Qs = sm;                   // [64][68]
    float* Ks = Qs + 64 * 68;         // [64][68]
    float* Vs = Ks + 64 * 68;         // [64][72]
    float* Ps = Vs + 64 * 72;         // [4][16][68]
    float* Mb = Ps + 4 * 16 * 68;     // [64]

    int t = threadIdx.x, lane = t & 31, w = t >> 5;
    int b = blockIdx.y >> 4, h = blockIdx.y & 15;
    int q0 = blockIdx.x * 64;
    const float* base = qkv + (size_t)b * SEQ * (3 * DIM) + h * (3 * HD);
    float* Pw = Ps + w * 16 * 68;

    int fr = t >> 4, fc = (t & 15) * 4;   // fill coords: 8 rows per thread step

    // Q tile
    #pragma unroll
    for (int i = 0; i < 8; i++) {
        int r = fr + i * 8;
        float4 q4 = *(const float4*)(base + (size_t)(q0 + r) * (3 * DIM) + fc);
        Qs[r*68+fc+0] = tf32r(q4.x); Qs[r*68+fc+1] = tf32r(q4.y);
        Qs[r*68+fc+2] = tf32r(q4.z); Qs[r*68+fc+3] = tf32r(q4.w);
    }

    float m0 = -INFINITY, m1 = -INFINITY, l0 = 0.f, l1 = 0.f;
    float o[8][4];
    #pragma unroll
    for (int nt = 0; nt < 8; nt++)
        #pragma unroll
        for (int i = 0; i < 4; i++) o[nt][i] = 0.f;

    // prefetch K block 0
    float4 kR[8];
    #pragma unroll
    for (int i = 0; i < 8; i++)
        kR[i] = *(const float4*)(base + (size_t)(fr + i * 8) * (3 * DIM) + HD + fc);

    for (int k0 = 0; k0 < SEQ; k0 += 64) {
        // 1) store K(i) + mask
        #pragma unroll
        for (int i = 0; i < 8; i++) {
            int r = fr + i * 8;
            Ks[r*68+fc+0] = tf32r(kR[i].x); Ks[r*68+fc+1] = tf32r(kR[i].y);
            Ks[r*68+fc+2] = tf32r(kR[i].z); Ks[r*68+fc+3] = tf32r(kR[i].w);
        }
        if (t < 64) Mb[t] = mask[b * SEQ + k0 + t] ? 0.f : -1e30f;
        __syncthreads();   // (A) Ks+Mb visible; prior PV reads of Vs done

        // 2) issue V(i) loads (retire under QK mma)
        float4 vR[8];
        #pragma unroll
        for (int i = 0; i < 8; i++)
            vR[i] = *(const float4*)(base + (size_t)(k0 + fr + i * 8) * (3 * DIM) + 2 * HD + fc);

        // 3) S = Q K^T
        float s[8][4];
        #pragma unroll
        for (int nt = 0; nt < 8; nt++)
            #pragma unroll
            for (int i = 0; i < 4; i++) s[nt][i] = 0.f;

        #pragma unroll
        for (int kt = 0; kt < 8; kt++) {
            int r = w * 16 + (lane >> 2);
            int c = kt * 8 + (lane & 3);
            uint32_t ah[4];
            ah[0] = __float_as_uint(Qs[r*68 + c]);
            ah[1] = __float_as_uint(Qs[(r+8)*68 + c]);
            ah[2] = __float_as_uint(Qs[r*68 + c + 4]);
            ah[3] = __float_as_uint(Qs[(r+8)*68 + c + 4]);
            #pragma unroll
            for (int nt = 0; nt < 8; nt++) {
                uint32_t bf[2];
                int n = nt * 8 + (lane >> 2);
                bf[0] = __float_as_uint(Ks[n*68 + c]);
                bf[1] = __float_as_uint(Ks[n*68 + c + 4]);
                mma8(s[nt], ah, bf);
            }
        }

        // 4) mask + online softmax
        float rm0 = -INFINITY, rm1 = -INFINITY;
        #pragma unroll
        for (int nt = 0; nt < 8; nt++) {
            float2 bi = *(float2*)&Mb[nt * 8 + 2 * (lane & 3)];
            s[nt][0] = s[nt][0] * SCALE + bi.x;
            s[nt][1] = s[nt][1] * SCALE + bi.y;
            s[nt][2] = s[nt][2] * SCALE + bi.x;
            s[nt][3] = s[nt][3] * SCALE + bi.y;
            rm0 = fmaxf(rm0, fmaxf(s[nt][0], s[nt][1]));
            rm1 = fmaxf(rm1, fmaxf(s[nt][2], s[nt][3]));
        }
        rm0 = fmaxf(rm0, __shfl_xor_sync(0xffffffffu, rm0, 1));
        rm0 = fmaxf(rm0, __shfl_xor_sync(0xffffffffu, rm0, 2));
        rm1 = fmaxf(rm1, __shfl_xor_sync(0xffffffffu, rm1, 1));
        rm1 = fmaxf(rm1, __shfl_xor_sync(0xffffffffu, rm1, 2));

        float mn0 = fmaxf(m0, rm0), mn1 = fmaxf(m1, rm1);
        float sc0 = __expf(m0 - mn0), sc1 = __expf(m1 - mn1);
        m0 = mn0; m1 = mn1;

        float ps0 = 0.f, ps1 = 0.f;
        int r = (lane >> 2);
        #pragma unroll
        for (int nt = 0; nt < 8; nt++) {
            float p0 = (s[nt][0] < -1e29f) ? 0.f : __expf(s[nt][0] - mn0);
            float p1 = (s[nt][1] < -1e29f) ? 0.f : __expf(s[nt][1] - mn0);
            float p2 = (s[nt][2] < -1e29f) ? 0.f : __expf(s[nt][2] - mn1);
            float p3 = (s[nt][3] < -1e29f) ? 0.f : __expf(s[nt][3] - mn1);
            ps0 += p0 + p1; ps1 += p2 + p3;
            int cc = nt * 8 + 2 * (lane & 3);
            *(float2*)&Pw[r * 68 + cc]       = make_float2(tf32r(p0), tf32r(p1));
            *(float2*)&Pw[(r + 8) * 68 + cc] = make_float2(tf32r(p2), tf32r(p3));
        }
        ps0 += __shfl_xor_sync(0xffffffffu, ps0, 1);
        ps0 += __shfl_xor_sync(0xffffffffu, ps0, 2);
        ps1 += __shfl_xor_sync(0xffffffffu, ps1, 1);
        ps1 += __shfl_xor_sync(0xffffffffu, ps1, 2);
        l0 = l0 * sc0 + ps0;
        l1 = l1 * sc1 + ps1;

        #pragma unroll
        for (int nt = 0; nt < 8; nt++) {
            o[nt][0] *= sc0; o[nt][1] *= sc0;
            o[nt][2] *= sc1; o[nt][3] *= sc1;
        }

        // 5) store V(i) (latency already covered by QK+softmax)
        #pragma unroll
        for (int i = 0; i < 8; i++) {
            int rr = fr + i * 8;
            Vs[rr*72+fc+0] = tf32r(vR[i].x); Vs[rr*72+fc+1] = tf32r(vR[i].y);
            Vs[rr*72+fc+2] = tf32r(vR[i].z); Vs[rr*72+fc+3] = tf32r(vR[i].w);
        }
        __syncthreads();   // (B) Vs visible; all Ks reads complete

        // 6) issue K(i+1) loads (retire under PV mma)
        if (k0 + 64 < SEQ) {
            #pragma unroll
            for (int i = 0; i < 8; i++)
                kR[i] = *(const float4*)(base + (size_t)(k0 + 64 + fr + i * 8) * (3 * DIM) + HD + fc);
        }

        // 7) O += P @ V
        #pragma unroll
        for (int kt = 0; kt < 8; kt++) {
            uint32_t pa[4];
            int rr = (lane >> 2), cc = kt * 8 + (lane & 3);
            pa[0] = __float_as_uint(Pw[rr * 68 + cc]);
            pa[1] = __float_as_uint(Pw[(rr + 8) * 68 + cc]);
            pa[2] = __float_as_uint(Pw[rr * 68 + cc + 4]);
            pa[3] = __float_as_uint(Pw[(rr + 8) * 68 + cc + 4]);
            #pragma unroll
            for (int nt = 0; nt < 8; nt++) {
                uint32_t bf[2];
                int n = nt * 8 + (lane >> 2);
                bf[0] = __float_as_uint(Vs[(kt * 8 + (lane & 3)) * 72 + n]);
                bf[1] = __float_as_uint(Vs[(kt * 8 + (lane & 3) + 4) * 72 + n]);
                mma8(o[nt], pa, bf);
            }
        }
    }

    float i0 = 1.f / l0, i1 = 1.f / l1;   // l already fully reduced in-loop
    int ra = b * SEQ + q0 + w * 16 + (lane >> 2);
    #pragma unroll
    for (int nt = 0; nt < 8; nt++) {
        int col = h * HD + nt * 8 + 2 * (lane & 3);
        *(float2*)(out + (size_t)ra * DIM + col) =
            make_float2(o[nt][0] * i0, o[nt][1] * i0);
        *(float2*)(out + (size_t)(ra + 8) * DIM + col) =
            make_float2(o[nt][2] * i1, o[nt][3] * i1);
    }
}

// ---------------------------------------------------------------------------
extern "C" void kernel_launch(void* const* d_in, const int* in_sizes, int n_in,
                              void* d_out, int out_size)
{
    (void)in_sizes; (void)n_in; (void)out_size;
    const float* x     = (const float*)d_in[0];
    const float* gamma = (const float*)d_in[1];
    const int*   mask  = (const int*)  d_in[2];
    const float* wqkv  = (const float*)d_in[3];
    const float* bqkv  = (const float*)d_in[4];
    const float* wo    = (const float*)d_in[5];
    const float* bo    = (const float*)d_in[6];
    float* out = (float*)d_out;

    float *qkv, *attn;
    cudaGetSymbolAddress((void**)&qkv,  g_qkv);
    cudaGetSymbolAddress((void**)&attn, g_attn);

    const int M = BSZ * SEQ;   // 4096

    cudaFuncSetAttribute(gemm_bf16<0>,
                         cudaFuncAttributeMaxDynamicSharedMemorySize, GEMM_SMEM_BYTES);
    cudaFuncSetAttribute(gemm_bf16<1>,
                         cudaFuncAttributeMaxDynamicSharedMemorySize, GEMM_SMEM_BYTES);

    // 1) QKV projection (bf16 split, double-buffered, reg prefetch)
    gemm_bf16<0><<<dim3(3 * DIM / 128, M / 128), 256, GEMM_SMEM_BYTES>>>(
        x, wqkv, bqkv, nullptr, qkv, M, 3 * DIM, DIM);

    // 2) Masked flash attention (tf32, software-pipelined loads)
    size_t smem = (size_t)(2 * 64 * 68 + 64 * 72 + 4 * 16 * 68 + 64) * sizeof(float);
    cudaFuncSetAttribute(attn_tf32,
                         cudaFuncAttributeMaxDynamicSharedMemorySize, (int)smem);
    attn_tf32<<<dim3(SEQ / 64, BSZ * NH), 128, smem>>>(qkv, mask, attn);

    // 3) Output projection + bias + (gamma+1)
    gemm_bf16<1><<<dim3(DIM / 128, M / 128), 256, GEMM_SMEM_BYTES>>>(
        attn, wo, bo, gamma, out, M, DIM, DIM);
}

// round 8
// speedup vs baseline: 1.5229x; 1.5229x over previous
#include <cuda_runtime.h>
#include <cuda_bf16.h>
#include <math.h>
#include <stdint.h>

#define BSZ 2
#define SEQ 2048
#define DIM 1024
#define NH  16
#define HD  64
#define SCALE 0.125f

// Scratch (no cudaMalloc allowed)
__device__ float g_qkv[(size_t)BSZ * SEQ * 3 * DIM];   // [B,S,3D]
__device__ float g_attn[(size_t)BSZ * SEQ * DIM];      // [B,S,D]

// ---------------------------------------------------------------------------
// helpers
// ---------------------------------------------------------------------------
__device__ __forceinline__ uint32_t f2t(float x) {
    uint32_t u; asm("cvt.rna.tf32.f32 %0, %1;" : "=r"(u) : "f"(x)); return u;
}
__device__ __forceinline__ float tf32r(float x) { return __uint_as_float(f2t(x)); }

__device__ __forceinline__ void mma8(float* c, const uint32_t* a, const uint32_t* b) {
    asm volatile(
        "mma.sync.aligned.m16n8k8.row.col.f32.tf32.tf32.f32 "
        "{%0,%1,%2,%3}, {%4,%5,%6,%7}, {%8,%9}, {%0,%1,%2,%3};\n"
        : "+f"(c[0]), "+f"(c[1]), "+f"(c[2]), "+f"(c[3])
        : "r"(a[0]), "r"(a[1]), "r"(a[2]), "r"(a[3]), "r"(b[0]), "r"(b[1]));
}

__device__ __forceinline__ void mma16(float* c, const uint32_t* a, uint32_t b0, uint32_t b1) {
    asm volatile(
        "mma.sync.aligned.m16n8k16.row.col.f32.bf16.bf16.f32 "
        "{%0,%1,%2,%3}, {%4,%5,%6,%7}, {%8,%9}, {%0,%1,%2,%3};\n"
        : "+f"(c[0]), "+f"(c[1]), "+f"(c[2]), "+f"(c[3])
        : "r"(a[0]), "r"(a[1]), "r"(a[2]), "r"(a[3]), "r"(b0), "r"(b1));
}

__device__ __forceinline__ void split2(float a, float b, uint32_t& h, uint32_t& l) {
    __nv_bfloat16 ah = __float2bfloat16(a), bh = __float2bfloat16(b);
    __nv_bfloat16 al = __float2bfloat16(a - __bfloat162float(ah));
    __nv_bfloat16 bl = __float2bfloat16(b - __bfloat162float(bh));
    __nv_bfloat162 hv, lv;
    hv.x = ah; hv.y = bh; lv.x = al; lv.y = bl;
    h = *reinterpret_cast<uint32_t*>(&hv);
    l = *reinterpret_cast<uint32_t*>(&lv);
}

// ---------------------------------------------------------------------------
// bf16 GEMM, 3-term split, single-buffer + register prefetch (R6 structure),
// CTA tile 128(M) x 64(N), BK=32, 256 threads, 8 warps 4(m)x2(n), warp 32x32.
// Sized for 2 CTAs/SM: ~120 regs (forced by launch_bounds), 30 KB smem.
// ---------------------------------------------------------------------------
template<int EPI>
__global__ __launch_bounds__(256, 2) void gemm_bf16(
    const float* __restrict__ A, const float* __restrict__ B,
    const float* __restrict__ bias, const float* __restrict__ gamma,
    float* __restrict__ C, int M, int N, int K)
{
    __shared__ __nv_bfloat16 Ah[128][40], Al[128][40];
    __shared__ __nv_bfloat16 Bh[64][40],  Bl[64][40];   // [n][k]

    int t = threadIdx.x, lane = t & 31, w = t >> 5;
    int wy = w >> 1, wx = w & 1;

    const float* Ab = A + (size_t)blockIdx.y * 128 * K;
    const float* Bb = B + (size_t)blockIdx.x * 64;

    // B fill coords: each thread owns column n, 8 consecutive k's
    int bn = t & 63, bkg = (t >> 6) * 8;

    float acc[2][4][4];
    #pragma unroll
    for (int mt = 0; mt < 2; mt++)
        #pragma unroll
        for (int nt = 0; nt < 4; nt++)
            #pragma unroll
            for (int i = 0; i < 4; i++) acc[mt][nt][i] = 0.f;

    float4 aR[4];
    float  bR[8];

    // prefetch tile 0
    #pragma unroll
    for (int i = 0; i < 4; i++) {
        int idx = t + i * 256;
        int r = idx >> 3, c4 = (idx & 7) * 4;
        aR[i] = *(const float4*)(Ab + (size_t)r * K + c4);
    }
    #pragma unroll
    for (int j = 0; j < 8; j++)
        bR[j] = Bb[(size_t)(bkg + j) * N + bn];

    const int ITERS = K / 32;
    for (int it = 0; it < ITERS; it++) {
        // store prefetched regs -> smem (split hi/lo)
        #pragma unroll
        for (int i = 0; i < 4; i++) {
            int idx = t + i * 256;
            int r = idx >> 3, c4 = (idx & 7) * 4;
            uint32_t h01, l01, h23, l23;
            split2(aR[i].x, aR[i].y, h01, l01);
            split2(aR[i].z, aR[i].w, h23, l23);
            *(uint2*)&Ah[r][c4] = make_uint2(h01, h23);
            *(uint2*)&Al[r][c4] = make_uint2(l01, l23);
        }
        {
            uint32_t h[4], l[4];
            split2(bR[0], bR[1], h[0], l[0]);
            split2(bR[2], bR[3], h[1], l[1]);
            split2(bR[4], bR[5], h[2], l[2]);
            split2(bR[6], bR[7], h[3], l[3]);
            *(uint2*)&Bh[bn][bkg]     = make_uint2(h[0], h[1]);
            *(uint2*)&Bh[bn][bkg + 4] = make_uint2(h[2], h[3]);
            *(uint2*)&Bl[bn][bkg]     = make_uint2(l[0], l[1]);
            *(uint2*)&Bl[bn][bkg + 4] = make_uint2(l[2], l[3]);
        }
        __syncthreads();

        // issue gmem loads for next tile (retire during mma)
        if (it + 1 < ITERS) {
            int k0n = (it + 1) * 32;
            #pragma unroll
            for (int i = 0; i < 4; i++) {
                int idx = t + i * 256;
                int r = idx >> 3, c4 = (idx & 7) * 4;
                aR[i] = *(const float4*)(Ab + (size_t)r * K + k0n + c4);
            }
            #pragma unroll
            for (int j = 0; j < 8; j++)
                bR[j] = Bb[(size_t)(k0n + bkg + j) * N + bn];
        }

        // mma phase
        #pragma unroll
        for (int ks = 0; ks < 2; ks++) {
            int kb = ks * 16 + (lane & 3) * 2;
            uint32_t ah[2][4], al[2][4];
            #pragma unroll
            for (int mt = 0; mt < 2; mt++) {
                int r = wy * 32 + mt * 16 + (lane >> 2);
                ah[mt][0] = *(uint32_t*)&Ah[r][kb];
                ah[mt][1] = *(uint32_t*)&Ah[r + 8][kb];
                ah[mt][2] = *(uint32_t*)&Ah[r][kb + 8];
                ah[mt][3] = *(uint32_t*)&Ah[r + 8][kb + 8];
                al[mt][0] = *(uint32_t*)&Al[r][kb];
                al[mt][1] = *(uint32_t*)&Al[r + 8][kb];
                al[mt][2] = *(uint32_t*)&Al[r][kb + 8];
                al[mt][3] = *(uint32_t*)&Al[r + 8][kb + 8];
            }
            #pragma unroll
            for (int nt = 0; nt < 4; nt++) {
                int n = wx * 32 + nt * 8 + (lane >> 2);
                uint32_t bh0 = *(uint32_t*)&Bh[n][kb];
                uint32_t bh1 = *(uint32_t*)&Bh[n][kb + 8];
                uint32_t bl0 = *(uint32_t*)&Bl[n][kb];
                uint32_t bl1 = *(uint32_t*)&Bl[n][kb + 8];
                #pragma unroll
                for (int mt = 0; mt < 2; mt++) {
                    mma16(acc[mt][nt], ah[mt], bh0, bh1);
                    mma16(acc[mt][nt], al[mt], bh0, bh1);
                    mma16(acc[mt][nt], ah[mt], bl0, bl1);
                }
            }
        }
        __syncthreads();
    }

    // Epilogue
    int r_base = blockIdx.y * 128 + wy * 32 + (lane >> 2);
    int c_base = blockIdx.x * 64 + wx * 32 + 2 * (lane & 3);
    #pragma unroll
    for (int nt = 0; nt < 4; nt++) {
        int col = c_base + nt * 8;
        float2 bi = *(const float2*)&bias[col];
        float g0 = 1.f, g1 = 1.f;
        if (EPI) {
            float2 gm = *(const float2*)&gamma[col];
            g0 = gm.x + 1.f; g1 = gm.y + 1.f;
        }
        #pragma unroll
        for (int mt = 0; mt < 2; mt++) {
            int ra = r_base + mt * 16;
            float2 v0, v1;
            v0.x = acc[mt][nt][0] + bi.x;
            v0.y = acc[mt][nt][1] + bi.y;
            v1.x = acc[mt][nt][2] + bi.x;
            v1.y = acc[mt][nt][3] + bi.y;
            if (EPI) { v0.x *= g0; v0.y *= g1; v1.x *= g0; v1.y *= g1; }
            *(float2*)(C + (size_t)ra * N + col)       = v0;
            *(float2*)(C + (size_t)(ra + 8) * N + col) = v1;
        }
    }
}

// ---------------------------------------------------------------------------
// Flash attention, tf32 warp mma — EXACT R6 version (known-good, 710us run).
// Single-term QK; l0/l1 fully reduced in-loop, no final re-reduction.
// ---------------------------------------------------------------------------
__global__ __launch_bounds__(128) void attn_tf32(
    const float* __restrict__ qkv, const int* __restrict__ mask,
    float* __restrict__ out)
{
    extern __shared__ float sm[];
    float* Qs = sm;                   // [64][68]
    float* Ks = Qs + 64 * 68;         // [64][68]
    float* Vs = Ks + 64 * 68;         // [64][72]
    float* Ps = Vs + 64 * 72;         // [4][16][68]
    float* Mb = Ps + 4 * 16 * 68;     // [64]

    int t = threadIdx.x, lane = t & 31, w = t >> 5;
    int b = blockIdx.y >> 4, h = blockIdx.y & 15;
    int q0 = blockIdx.x * 64;
    const float* base = qkv + (size_t)b * SEQ * (3 * DIM) + h * (3 * HD);
    float* Pw = Ps + w * 16 * 68;

    #pragma unroll
    for (int i = 0; i < 8; i++) {
        int idx = t + i * 128;
        int r = idx >> 4, c = (idx & 15) * 4;
        float4 q4 = *(const float4*)(base + (size_t)(q0 + r) * (3 * DIM) + c);
        Qs[r*68+c+0] = tf32r(q4.x); Qs[r*68+c+1] = tf32r(q4.y);
        Qs[r*68+c+2] = tf32r(q4.z); Qs[r*68+c+3] = tf32r(q4.w);
    }

    float m0 = -INFINITY, m1 = -INFINITY, l0 = 0.f, l1 = 0.f;
    float o[8][4];
    #pragma unroll
    for (int nt = 0; nt < 8; nt++)
        #pragma unroll
        for (int i = 0; i < 4; i++) o[nt][i] = 0.f;

    for (int k0 = 0; k0 < SEQ; k0 += 64) {
        __syncthreads();
        #pragma unroll
        for (int i = 0; i < 8; i++) {
            int idx = t + i * 128;
            int r = idx >> 4, c = (idx & 15) * 4;
            const float* rp = base + (size_t)(k0 + r) * (3 * DIM);
            float4 k4 = *(const float4*)(rp + HD + c);
            Ks[r*68+c+0] = tf32r(k4.x); Ks[r*68+c+1] = tf32r(k4.y);
            Ks[r*68+c+2] = tf32r(k4.z); Ks[r*68+c+3] = tf32r(k4.w);
            float4 v4 = *(const float4*)(rp + 2 * HD + c);
            Vs[r*72+c+0] = tf32r(v4.x); Vs[r*72+c+1] = tf32r(v4.y);
            Vs[r*72+c+2] = tf32r(v4.z); Vs[r*72+c+3] = tf32r(v4.w);
        }
        if (t < 64) Mb[t] = mask[b * SEQ + k0 + t] ? 0.f : -1e30f;
        __syncthreads();

        float s[8][4];
        #pragma unroll
        for (int nt = 0; nt < 8; nt++)
            #pragma unroll
            for (int i = 0; i < 4; i++) s[nt][i] = 0.f;

        #pragma unroll
        for (int kt = 0; kt < 8; kt++) {
            int r = w * 16 + (lane >> 2);
            int c = kt * 8 + (lane & 3);
            uint32_t ah[4];
            ah[0] = __float_as_uint(Qs[r*68 + c]);
            ah[1] = __float_as_uint(Qs[(r+8)*68 + c]);
            ah[2] = __float_as_uint(Qs[r*68 + c + 4]);
            ah[3] = __float_as_uint(Qs[(r+8)*68 + c + 4]);
            #pragma unroll
            for (int nt = 0; nt < 8; nt++) {
                uint32_t bf[2];
                int n = nt * 8 + (lane >> 2);
                bf[0] = __float_as_uint(Ks[n*68 + c]);
                bf[1] = __float_as_uint(Ks[n*68 + c + 4]);
                mma8(s[nt], ah, bf);
            }
        }

        float rm0 = -INFINITY, rm1 = -INFINITY;
        #pragma unroll
        for (int nt = 0; nt < 8; nt++) {
            float2 bi = *(float2*)&Mb[nt * 8 + 2 * (lane & 3)];
            s[nt][0] = s[nt][0] * SCALE + bi.x;
            s[nt][1] = s[nt][1] * SCALE + bi.y;
            s[nt][2] = s[nt][2] * SCALE + bi.x;
            s[nt][3] = s[nt][3] * SCALE + bi.y;
            rm0 = fmaxf(rm0, fmaxf(s[nt][0], s[nt][1]));
            rm1 = fmaxf(rm1, fmaxf(s[nt][2], s[nt][3]));
        }
        rm0 = fmaxf(rm0, __shfl_xor_sync(0xffffffffu, rm0, 1));
        rm0 = fmaxf(rm0, __shfl_xor_sync(0xffffffffu, rm0, 2));
        rm1 = fmaxf(rm1, __shfl_xor_sync(0xffffffffu, rm1, 1));
        rm1 = fmaxf(rm1, __shfl_xor_sync(0xffffffffu, rm1, 2));

        float mn0 = fmaxf(m0, rm0), mn1 = fmaxf(m1, rm1);
        float sc0 = __expf(m0 - mn0), sc1 = __expf(m1 - mn1);
        m0 = mn0; m1 = mn1;

        float ps0 = 0.f, ps1 = 0.f;
        int r = (lane >> 2);
        #pragma unroll
        for (int nt = 0; nt < 8; nt++) {
            float p0 = (s[nt][0] < -1e29f) ? 0.f : __expf(s[nt][0] - mn0);
            float p1 = (s[nt][1] < -1e29f) ? 0.f : __expf(s[nt][1] - mn0);
            float p2 = (s[nt][2] < -1e29f) ? 0.f : __expf(s[nt][2] - mn1);
            float p3 = (s[nt][3] < -1e29f) ? 0.f : __expf(s[nt][3] - mn1);
            ps0 += p0 + p1; ps1 += p2 + p3;
            int cc = nt * 8 + 2 * (lane & 3);
            *(float2*)&Pw[r * 68 + cc]       = make_float2(tf32r(p0), tf32r(p1));
            *(float2*)&Pw[(r + 8) * 68 + cc] = make_float2(tf32r(p2), tf32r(p3));
        }
        ps0 += __shfl_xor_sync(0xffffffffu, ps0, 1);
        ps0 += __shfl_xor_sync(0xffffffffu, ps0, 2);
        ps1 += __shfl_xor_sync(0xffffffffu, ps1, 1);
        ps1 += __shfl_xor_sync(0xffffffffu, ps1, 2);
        l0 = l0 * sc0 + ps0;
        l1 = l1 * sc1 + ps1;

        #pragma unroll
        for (int nt = 0; nt < 8; nt++) {
            o[nt][0] *= sc0; o[nt][1] *= sc0;
            o[nt][2] *= sc1; o[nt][3] *= sc1;
        }
        __syncwarp();

        #pragma unroll
        for (int kt = 0; kt < 8; kt++) {
            uint32_t pa[4];
            int rr = (lane >> 2), cc = kt * 8 + (lane & 3);
            pa[0] = __float_as_uint(Pw[rr * 68 + cc]);
            pa[1] = __float_as_uint(Pw[(rr + 8) * 68 + cc]);
            pa[2] = __float_as_uint(Pw[rr * 68 + cc + 4]);
            pa[3] = __float_as_uint(Pw[(rr + 8) * 68 + cc + 4]);
            #pragma unroll
            for (int nt = 0; nt < 8; nt++) {
                uint32_t bf[2];
                int n = nt * 8 + (lane >> 2);
                bf[0] = __float_as_uint(Vs[(kt * 8 + (lane & 3)) * 72 + n]);
                bf[1] = __float_as_uint(Vs[(kt * 8 + (lane & 3) + 4) * 72 + n]);
                mma8(o[nt], pa, bf);
            }
        }
        __syncwarp();
    }

    float i0 = 1.f / l0, i1 = 1.f / l1;
    int ra = b * SEQ + q0 + w * 16 + (lane >> 2);
    #pragma unroll
    for (int nt = 0; nt < 8; nt++) {
        int col = h * HD + nt * 8 + 2 * (lane & 3);
        *(float2*)(out + (size_t)ra * DIM + col) =
            make_float2(o[nt][0] * i0, o[nt][1] * i0);
        *(float2*)(out + (size_t)(ra + 8) * DIM + col) =
            make_float2(o[nt][2] * i1, o[nt][3] * i1);
    }
}

// ---------------------------------------------------------------------------
extern "C" void kernel_launch(void* const* d_in, const int* in_sizes, int n_in,
                              void* d_out, int out_size)
{
    (void)in_sizes; (void)n_in; (void)out_size;
    const float* x     = (const float*)d_in[0];
    const float* gamma = (const float*)d_in[1];
    const int*   mask  = (const int*)  d_in[2];
    const float* wqkv  = (const float*)d_in[3];
    const float* bqkv  = (const float*)d_in[4];
    const float* wo    = (const float*)d_in[5];
    const float* bo    = (const float*)d_in[6];
    float* out = (float*)d_out;

    float *qkv, *attn;
    cudaGetSymbolAddress((void**)&qkv,  g_qkv);
    cudaGetSymbolAddress((void**)&attn, g_attn);

    const int M = BSZ * SEQ;   // 4096

    // 1) QKV projection (bf16 split, 128x64 tile, 2 CTAs/SM)
    gemm_bf16<0><<<dim3(3 * DIM / 64, M / 128), 256>>>(
        x, wqkv, bqkv, nullptr, qkv, M, 3 * DIM, DIM);

    // 2) Masked flash attention (tf32, R6 version)
    size_t smem = (size_t)(2 * 64 * 68 + 64 * 72 + 4 * 16 * 68 + 64) * sizeof(float);
    cudaFuncSetAttribute(attn_tf32,
                         cudaFuncAttributeMaxDynamicSharedMemorySize, (int)smem);
    attn_tf32<<<dim3(SEQ / 64, BSZ * NH), 128, smem>>>(qkv, mask, attn);

    // 3) Output projection + bias + (gamma+1)
    gemm_bf16<1><<<dim3(DIM / 64, M / 128), 256>>>(
        attn, wo, bo, gamma, out, M, DIM, DIM);
}